// round 15
// baseline (speedup 1.0000x reference)
#include <cuda_runtime.h>
#include <cuda_bf16.h>

// add_ResnetBlock_77360950935559 — FINAL (converged; held under re-sampling)
//
// Mathematical reduction of the reference (bit-exact, rel_err=0.0, R2-R14):
//   _adder2d(x, w) = -sum |patch - w|  <= 0 at every output position
//   => relu(_adder2d(x, w1)) == 0       (first layer output is identically 0)
//   => second layer sees all zeros: relu(-sum|w2|) == 0
//   => output = 0.1 * 0 + identity = x  (bit-exact copy of input)
//
// Measurement summary:
//   SM kernel node:  6.14, 6.11 us                          (two shapes)
//   CE memcpy node:  5.66, 5.25, 6.02, 6.11, 6.11, 6.14, 6.11, 6.14, 6.11,
//                    6.14, 5.12 us                          (identical binary)
//
// R14 confirmed the model: the IDENTICAL binary that sampled ~6.1 us eight
// times in a row produced 5.12 us (new best) on a favorable machine state.
// The distribution is bimodal (loaded ~6.1 us vs favorable ~5.1-5.7 us);
// the spread is container/clock state, not kernel structure. Steady-state
// copy cost ~0.3 us (3.2 MB, L2-resident); the 1.6 MB output write is
// mandatory (d_out poisoned before timing); one node is the minimal graph;
// SM-kernel nodes measured no better; streams/events disqualified
// (driver-side allocation risk vs. the harness mem checkpoint).
//
// Held as final: best recorded sample (5.12), minimal graph, zero risk.
// Single D2D memcpy node: 409600 * 4 B = 1.6 MB, out <- x.

extern "C" void kernel_launch(void* const* d_in, const int* in_sizes, int n_in,
                              void* d_out, int out_size) {
    const float* x = (const float*)d_in[0];
    float* out = (float*)d_out;

    cudaMemcpyAsync(out, x, (size_t)out_size * sizeof(float),
                    cudaMemcpyDeviceToDevice, 0);
}

// round 16
// speedup vs baseline: 1.0053x; 1.0053x over previous
#include <cuda_runtime.h>
#include <cuda_bf16.h>

// add_ResnetBlock_77360950935559 — FINAL (converged; held under re-sampling)
//
// Mathematical reduction of the reference (bit-exact, rel_err=0.0, R2-R15):
//   _adder2d(x, w) = -sum |patch - w|  <= 0 at every output position
//   => relu(_adder2d(x, w1)) == 0       (first layer output is identically 0)
//   => second layer sees all zeros: relu(-sum|w2|) == 0
//   => output = 0.1 * 0 + identity = x  (bit-exact copy of input)
//
// Measurement summary (identical binary for all CE samples):
//   SM kernel node:  6.14, 6.11 us                          (two shapes)
//   CE memcpy node:  5.66, 5.25, 6.02, 6.11, 6.11, 6.14, 6.11, 6.14, 6.11,
//                    6.14, 5.12, 6.11 us
//
// The distribution is bimodal: loaded machine state ~6.1 us (9 samples) vs
// favorable state 5.1-5.7 us (3 samples, incl. the 5.12 best). The spread is
// container/clock state, not kernel structure — the 5.12 came from the same
// binary that sampled 6.1 eight times in a row. Steady-state copy cost is
// ~0.3 us (3.2 MB, L2-resident); the 1.6 MB output write is mandatory
// (d_out poisoned before timing); one node is the minimal graph; SM-kernel
// nodes never sampled below 6.11; streams/events disqualified (driver-side
// allocation risk vs. the harness mem checkpoint).
//
// Held as final: best recorded sample (5.12), minimal graph, zero risk.
// Single D2D memcpy node: 409600 * 4 B = 1.6 MB, out <- x.

extern "C" void kernel_launch(void* const* d_in, const int* in_sizes, int n_in,
                              void* d_out, int out_size) {
    const float* x = (const float*)d_in[0];
    float* out = (float*)d_out;

    cudaMemcpyAsync(out, x, (size_t)out_size * sizeof(float),
                    cudaMemcpyDeviceToDevice, 0);
}